// round 16
// baseline (speedup 1.0000x reference)
#include <cuda_runtime.h>

// conv2d 4096x4096 (fp32) * 15x15 VALID + bias -> 4082x4082 (fp32)
// R16: R12 operating point (FFMA2 phase-shifted dual accumulators, rolling
//      staged window, 5 blocks/SM) with the constant-port pressure halved:
//      cW rows padded to 16 floats; each c-step loads its weight pair as ONE
//      LDC.64 (float2) -> 8 LDCs/ky instead of 15, no back-to-back LDC stalls.
//      Padded layout filled via a single pitched D2D memcpy node.

#define H 4096
#define W 4096
#define KH 15
#define KW 15
#define OH 4082
#define OW 4082

#define BX 192          // 16 threads * RX=12
#define BY 16
#define NT 256
#define RX 12           // 48B lane stride: odd multiple of 16B -> conflict-free

#define IN_H (BY + KH - 1)          // 30
#define SROW 208                    // pad 192+14 -> 208 (52 float4)

typedef unsigned long long ull;

__constant__ __align__(16) float cW[KH * 16];   // rows padded to 16 floats

__device__ __forceinline__ ull pack2(float lo, float hi) {
    ull r; asm("mov.b64 %0, {%1, %2};" : "=l"(r) : "f"(lo), "f"(hi)); return r;
}
__device__ __forceinline__ void unpack2(ull v, float& lo, float& hi) {
    asm("mov.b64 {%0, %1}, %2;" : "=f"(lo), "=f"(hi) : "l"(v));
}
__device__ __forceinline__ ull fma2(ull a, ull b, ull c) {
    ull d; asm("fma.rn.f32x2 %0, %1, %2, %3;" : "=l"(d) : "l"(a), "l"(b), "l"(c)); return d;
}

__global__ __launch_bounds__(NT, 4)
void conv2d_r16_kernel(const float* __restrict__ X,
                       const float* __restrict__ bias,
                       float* __restrict__ out)
{
    __shared__ __align__(16) float sX[IN_H][SROW];

    const int tid = threadIdx.x;
    const int bx = blockIdx.x * BX;
    const int by = blockIdx.y * BY;

    // ---- stage input tile: 30 rows x 208 cols, float4, guarded ----
    const int NV = IN_H * (SROW / 4);     // 30*52 = 1560
    for (int idx = tid; idx < NV; idx += NT) {
        int r  = idx / (SROW / 4);
        int c4 = idx - r * (SROW / 4);
        int gr = by + r;
        int gc = bx + c4 * 4;
        float4 v = make_float4(0.f, 0.f, 0.f, 0.f);
        if (gr < H) {
            const float* src = X + (long)gr * W + gc;
            if (gc + 3 < W) v = *(const float4*)src;
            else {
                if (gc + 0 < W) v.x = src[0];
                if (gc + 1 < W) v.y = src[1];
                if (gc + 2 < W) v.z = src[2];
                if (gc + 3 < W) v.w = src[3];
            }
        }
        *(float4*)&sX[r][c4 * 4] = v;
    }
    __syncthreads();

    const int tx = tid & 15;
    const int ty = tid >> 4;
    const int ox = tx * RX;               // conflict-free, 16B aligned
    const float b0 = bias[0];

    ull accA[6];                          // (o_{2j}, o_{2j+1}); bias pre-folded
    ull accB[7];                          // (o_{2j-1}, o_{2j})
    {
        const ull bb = pack2(b0, b0);
        #pragma unroll
        for (int j = 0; j < 6; ++j) accA[j] = bb;
        #pragma unroll
        for (int j = 0; j < 7; ++j) accB[j] = 0ull;
    }

    #pragma unroll 1
    for (int ky = 0; ky < KH; ++ky) {
        const ulonglong2* row = (const ulonglong2*)&sX[ty + ky][ox];
        const float* rowf = &sX[ty + ky][ox];
        const int wb = ky * 16;

        // rolling window with staging lead:
        // v[0..3] up front; v4@c=0 (use c=2), v5@c=1 (use c=4), v6@c=2 (use c=6)
        ulonglong2 v[6];
        ull v6;
        v[0] = row[0]; v[1] = row[1]; v[2] = row[2]; v[3] = row[3];

        #pragma unroll
        for (int c = 0; c < 8; ++c) {
            if (c == 0) v[4] = row[4];
            if (c == 1) v[5] = row[5];
            if (c == 2) v6 = *(const ull*)(rowf + 24);   // P12 (8B suffices)

            // ONE LDC.64 per c-step: (w_{2c}, w_{2c+1}) -- 8B aligned (2c even)
            const float2 wp = *(const float2*)&cW[wb + 2 * c];
            const ull wpx = pack2(wp.x, wp.x);
            // even tap a=2c: accA[j] += w_{2c} * P[j+c], j=0..5
            #pragma unroll
            for (int j = 0; j < 6; ++j) {
                const int p = j + c;
                const ull Pp = (p == 12) ? v6 : ((p & 1) ? v[p >> 1].y : v[p >> 1].x);
                accA[j] = fma2(wpx, Pp, accA[j]);
            }
            // odd tap a=2c+1: accB[j] += w_{2c+1} * P[j+c], j=0..6
            if (c < 7) {
                const ull wpy = pack2(wp.y, wp.y);
                #pragma unroll
                for (int j = 0; j < 7; ++j) {
                    const int p = j + c;
                    const ull Pp = (p == 12) ? v6 : ((p & 1) ? v[p >> 1].y : v[p >> 1].x);
                    accB[j] = fma2(wpy, Pp, accB[j]);
                }
            }
        }
    }

    // ---- epilogue: recombine phases, guarded float2 stores ----
    const int orow = by + ty;
    if (orow < OH) {
        float* orp = out + (long)orow * OW;
        float alo[6], ahi[6], blo[7], bhi[7];
        #pragma unroll
        for (int j = 0; j < 6; ++j) unpack2(accA[j], alo[j], ahi[j]);
        #pragma unroll
        for (int j = 0; j < 7; ++j) unpack2(accB[j], blo[j], bhi[j]);
        #pragma unroll
        for (int j = 0; j < 6; ++j) {
            int ocol = bx + ox + 2 * j;      // even; OW even -> pair fully in or out
            if (ocol < OW) {
                float2 st;
                st.x = alo[j] + bhi[j];          // o_{2j}   (bias in accA)
                st.y = ahi[j] + blo[j + 1];      // o_{2j+1}
                *(float2*)(orp + ocol) = st;
            }
        }
    }
}

extern "C" void kernel_launch(void* const* d_in, const int* in_sizes, int n_in,
                              void* d_out, int out_size)
{
    const float* X  = (const float*)d_in[0];
    const float* Wt = (const float*)d_in[1];
    const float* bs = (const float*)d_in[2];
    float* out = (float*)d_out;

    // weights -> padded constant rows (single pitched D2D memcpy node)
    void* csym = nullptr;
    cudaGetSymbolAddress(&csym, cW);
    cudaMemcpy2DAsync(csym, 16 * sizeof(float),          // dst, dpitch (64B rows)
                      Wt,   KW * sizeof(float),          // src, spitch (60B rows)
                      KW * sizeof(float), KH,            // width bytes, height
                      cudaMemcpyDeviceToDevice, 0);

    dim3 grid((OW + BX - 1) / BX, (OH + BY - 1) / BY);   // 22 x 256
    conv2d_r16_kernel<<<grid, NT>>>(X, bs, out);
}

// round 17
// speedup vs baseline: 1.7555x; 1.7555x over previous
#include <cuda_runtime.h>
#include <cstdint>

// conv2d 4096x4096 (fp32) * 15x15 VALID + bias -> 4082x4082 (fp32)
// R17: tensor-core banded implicit GEMM.
//   out[i, J+n] = sum_q X[i+ky, J+q] * B_ky[q, n],  B_ky[q,n] = W[ky, q-n] (banded, q<24)
//   mma.sync.m16n8k8.row.col.f32.tf32.tf32.f32, fp32 accumulate, cvt.rna tf32 inputs.
//   Block: 256 thr = 8 warps (2 row x 4 col), output 32x128 per block.
//   Warp: 16 rows x 32 cols = 4 n-tiles; per ky: 6 shared A-fragments, 3 B-slices, 12 MMAs.

#define H 4096
#define W 4096
#define KH 15
#define KW 15
#define OH 4082
#define OW 4082

#define BXo 128
#define BYo 32
#define NT 256

#define IN_H 46            // BYo + KH - 1
#define SROW 148           // 128+14 -> pad to 148 (37 float4; 148%32=20 -> conflict-free frags)

__device__ __forceinline__ uint32_t tf32r(float x) {
    uint32_t r; asm("cvt.rna.tf32.f32 %0, %1;" : "=r"(r) : "f"(x)); return r;
}

__device__ __forceinline__ void mma_tf32(float c[4],
                                         uint32_t a0, uint32_t a1, uint32_t a2, uint32_t a3,
                                         uint32_t b0, uint32_t b1) {
    asm volatile(
        "mma.sync.aligned.m16n8k8.row.col.f32.tf32.tf32.f32 "
        "{%0,%1,%2,%3}, {%4,%5,%6,%7}, {%8,%9}, {%0,%1,%2,%3};"
        : "+f"(c[0]), "+f"(c[1]), "+f"(c[2]), "+f"(c[3])
        : "r"(a0), "r"(a1), "r"(a2), "r"(a3), "r"(b0), "r"(b1));
}

__global__ __launch_bounds__(NT, 3)
void conv2d_r17_kernel(const float* __restrict__ X,
                       const float* __restrict__ Wt,
                       const float* __restrict__ bias,
                       float* __restrict__ out)
{
    __shared__ __align__(16) float sX[IN_H][SROW];      // tf32-rounded input tile
    __shared__ float sB[KH * 3 * 64];                    // banded weights [ky][s][q8][n]

    const int tid = threadIdx.x;
    const int bx = blockIdx.x * BXo;
    const int by = blockIdx.y * BYo;
    const float b0 = bias[0];

    // ---- stage input tile (tf32-rounded), float4, guarded ----
    const int NV = IN_H * (SROW / 4);    // 46*37 = 1702
    for (int idx = tid; idx < NV; idx += NT) {
        int r  = idx / (SROW / 4);
        int c4 = idx - r * (SROW / 4);
        int gr = by + r;
        int gc = bx + c4 * 4;
        float4 v = make_float4(0.f, 0.f, 0.f, 0.f);
        if (gr < H) {
            const float* src = X + (long)gr * W + gc;
            if (gc + 3 < W) v = *(const float4*)src;
            else {
                if (gc + 0 < W) v.x = src[0];
                if (gc + 1 < W) v.y = src[1];
                if (gc + 2 < W) v.z = src[2];
                if (gc + 3 < W) v.w = src[3];
            }
        }
        float4 t;
        t.x = __uint_as_float(tf32r(v.x));
        t.y = __uint_as_float(tf32r(v.y));
        t.z = __uint_as_float(tf32r(v.z));
        t.w = __uint_as_float(tf32r(v.w));
        *(float4*)&sX[r][c4 * 4] = t;
    }

    // ---- stage banded weight matrices: sB[((ky*3+s)*64) + q8*8 + n] = W[ky, q8+8s-n] ----
    for (int i = tid; i < KH * 3 * 64; i += NT) {
        int ky = i / 192;
        int r  = i - ky * 192;
        int s  = r >> 6;
        int q8 = (r >> 3) & 7;
        int n  = r & 7;
        int kx = q8 + 8 * s - n;
        float w = (kx >= 0 && kx < KW) ? Wt[ky * KW + kx] : 0.f;
        sB[i] = __uint_as_float(tf32r(w));
    }
    __syncthreads();

    const int wid  = tid >> 5;
    const int lane = tid & 31;
    const int rw = wid >> 2;            // row half (0/1)
    const int cw = wid & 3;             // col quarter (0..3)
    const int r4 = lane >> 2;           // fragment row 0..7
    const int cl = lane & 3;            // fragment k-col 0..3

    float acc[4][4];                    // [n-tile v][c0..c3], bias pre-folded
    #pragma unroll
    for (int v = 0; v < 4; ++v)
        #pragma unroll
        for (int e = 0; e < 4; ++e) acc[v][e] = b0;

    const uint32_t* abase = (const uint32_t*)&sX[rw * 16 + r4][cw * 32 + cl];
    const uint32_t* bbase = (const uint32_t*)&sB[cl * 8 + (lane >> 2)];

    #pragma unroll 1
    for (int ky = 0; ky < KH; ++ky) {
        const uint32_t* ap = abase + ky * SROW;
        const uint32_t* bp = bbase + ky * 192;

        // 6 A-fragments covering X cols cw*32 + 8u + [0,8), rows (+0,+8)
        uint32_t xf[6][4];
        #pragma unroll
        for (int u = 0; u < 6; ++u) {
            xf[u][0] = ap[8 * u];
            xf[u][1] = ap[8 * u + 8 * SROW];
            xf[u][2] = ap[8 * u + 4];
            xf[u][3] = ap[8 * u + 4 + 8 * SROW];
        }
        // 3 B-slices
        uint32_t bf[3][2];
        #pragma unroll
        for (int s = 0; s < 3; ++s) {
            bf[s][0] = bp[s * 64];
            bf[s][1] = bp[s * 64 + 32];
        }
        // 12 MMAs: out-tile v uses A-fragments v+s with B-slice s
        #pragma unroll
        for (int v = 0; v < 4; ++v)
            #pragma unroll
            for (int s = 0; s < 3; ++s)
                mma_tf32(acc[v], xf[v + s][0], xf[v + s][1], xf[v + s][2], xf[v + s][3],
                         bf[s][0], bf[s][1]);
    }

    // ---- epilogue: guarded float2 stores ----
    const int orow  = by + rw * 16 + r4;        // and +8
    const int ocolb = bx + cw * 32 + cl * 2;
    #pragma unroll
    for (int v = 0; v < 4; ++v) {
        int oc = ocolb + v * 8;                 // even; OW even -> pair fully in or out
        if (oc < OW) {
            if (orow < OH)
                *(float2*)(out + (long)orow * OW + oc) = make_float2(acc[v][0], acc[v][1]);
            if (orow + 8 < OH)
                *(float2*)(out + (long)(orow + 8) * OW + oc) = make_float2(acc[v][2], acc[v][3]);
        }
    }
}

extern "C" void kernel_launch(void* const* d_in, const int* in_sizes, int n_in,
                              void* d_out, int out_size)
{
    const float* X  = (const float*)d_in[0];
    const float* Wt = (const float*)d_in[1];
    const float* bs = (const float*)d_in[2];
    float* out = (float*)d_out;

    dim3 grid((OW + BXo - 1) / BXo, (OH + BYo - 1) / BYo);   // 32 x 128
    conv2d_r17_kernel<<<grid, NT>>>(X, Wt, bs, out);
}